// round 3
// baseline (speedup 1.0000x reference)
#include <cuda_runtime.h>
#include <math.h>

#define BB 2
#define NSEQ 2048
#define DMODEL 512
#define VOCAB 32000
#define DEPTH 6
#define NH 8
#define DH 64
#define DFF 2048
#define MROWS (BB * NSEQ)          // 4096
#define RES_SCALE 1.8612097182041991f   // (2*6)^0.25
#define ATT_SCALE 8.0f
#define EPS_LN 1e-5f
#define EPS_L2 1e-12f

// -------- scratch (device globals; no runtime allocation allowed) --------
__device__ float g_h[MROWS * DMODEL];
__device__ float g_q[MROWS * DMODEL];
__device__ float g_k[MROWS * DMODEL];
__device__ float g_v[MROWS * DMODEL];
__device__ float g_o[MROWS * DMODEL];
__device__ float g_ff[MROWS * DFF];

// ------------------------- embedding -------------------------
__global__ void embed_kernel(const int* __restrict__ x,
                             const float* __restrict__ tok,
                             const float* __restrict__ pos) {
    int row = blockIdx.x;          // 0..MROWS-1
    int n = row % NSEQ;
    int t = x[row];
    int c = threadIdx.x * 4;       // 128 threads * 4 = 512
    float4 a = *(const float4*)&tok[(size_t)t * DMODEL + c];
    float4 p = *(const float4*)&pos[(size_t)n * DMODEL + c];
    a.x += p.x; a.y += p.y; a.z += p.z; a.w += p.w;
    *(float4*)&g_h[(size_t)row * DMODEL + c] = a;
}

// ------------------------- generic fp32 GEMM -------------------------
// C[M,N] = A[M,K] @ B[K,N], all row-major. M%128==0, N%128==0, K%8==0.
// EPI: 0 = none, 1 = exact GELU on output.
template <int EPI>
__global__ __launch_bounds__(256) void gemm_kernel(
    const float* __restrict__ A, const float* __restrict__ Bw,
    float* __restrict__ C, int Md, int Nd, int Kd) {
    __shared__ float As[8][128];
    __shared__ float Bs[8][128];

    int rowBase = blockIdx.y * 128;
    int colBase = blockIdx.x * 128;
    int tid = threadIdx.x;
    int tx = tid & 15;         // 0..15 (N dir)
    int ty = tid >> 4;         // 0..15 (M dir)

    int aRow = tid >> 1;            // 0..127
    int aCol = (tid & 1) * 4;       // 0 or 4
    int bRow = tid >> 5;            // 0..7
    int bCol = (tid & 31) * 4;      // 0..124

    float acc[8][8];
#pragma unroll
    for (int i = 0; i < 8; i++)
#pragma unroll
        for (int j = 0; j < 8; j++) acc[i][j] = 0.f;

    const float* aPtr = A + (size_t)(rowBase + aRow) * Kd + aCol;
    const float* bPtr = Bw + (size_t)bRow * Nd + colBase + bCol;

    for (int k0 = 0; k0 < Kd; k0 += 8) {
        float4 a4 = *(const float4*)(aPtr + k0);
        As[aCol + 0][aRow] = a4.x;
        As[aCol + 1][aRow] = a4.y;
        As[aCol + 2][aRow] = a4.z;
        As[aCol + 3][aRow] = a4.w;
        float4 b4 = *(const float4*)(bPtr + (size_t)k0 * Nd);
        *(float4*)&Bs[bRow][bCol] = b4;
        __syncthreads();
#pragma unroll
        for (int kk = 0; kk < 8; kk++) {
            float4 a0 = *(const float4*)&As[kk][ty * 8];
            float4 a1 = *(const float4*)&As[kk][ty * 8 + 4];
            float4 b0 = *(const float4*)&Bs[kk][tx * 8];
            float4 b1 = *(const float4*)&Bs[kk][tx * 8 + 4];
            float ar[8] = {a0.x, a0.y, a0.z, a0.w, a1.x, a1.y, a1.z, a1.w};
            float br[8] = {b0.x, b0.y, b0.z, b0.w, b1.x, b1.y, b1.z, b1.w};
#pragma unroll
            for (int i = 0; i < 8; i++)
#pragma unroll
                for (int j = 0; j < 8; j++) acc[i][j] += ar[i] * br[j];
        }
        __syncthreads();
    }

    const float gc = 0.70710678118654752f;
#pragma unroll
    for (int i = 0; i < 8; i++) {
        if (EPI == 1) {
#pragma unroll
            for (int j = 0; j < 8; j++) {
                float xv = acc[i][j];
                acc[i][j] = 0.5f * xv * (1.0f + erff(xv * gc));
            }
        }
        float* cPtr = C + (size_t)(rowBase + ty * 8 + i) * Nd + colBase + tx * 8;
        float4 v0 = {acc[i][0], acc[i][1], acc[i][2], acc[i][3]};
        float4 v1 = {acc[i][4], acc[i][5], acc[i][6], acc[i][7]};
        *(float4*)cPtr = v0;
        *(float4*)(cPtr + 4) = v1;
    }
}

// ------------------------- flash causal attention -------------------------
// Cosine-sim attention: q,k l2-normalized -> scores in [-8,8], so softmax
// uses a FIXED max of 8 (no online rescaling needed; shift-invariant).
// Block: 64 threads, 64 queries. Tiles [DH][64] (transposed) in SMEM.
#define BQ 64
#define BKV 64
__global__ __launch_bounds__(64) void flash_kernel(
    const float* __restrict__ Q, const float* __restrict__ K,
    const float* __restrict__ V, float* __restrict__ O) {
    __shared__ float qs[DH][BQ];
    __shared__ float ks[DH][BKV];
    __shared__ float vs[DH][BKV];

    int qt = blockIdx.x;
    int bh = blockIdx.y;
    int b = bh / NH, h = bh % NH;
    int tid = threadIdx.x;
    int q0 = qt * BQ;

    // load + l2-normalize own query row into own SMEM column (no sync needed)
    {
        const float* qp = Q + ((size_t)(b * NSEQ + q0 + tid) * NH + h) * DH;
        float nrm = 0.f;
#pragma unroll
        for (int d = 0; d < DH; d++) { float xv = qp[d]; qs[d][tid] = xv; nrm += xv * xv; }
        float inv = 1.0f / fmaxf(sqrtf(nrm), EPS_L2);
#pragma unroll
        for (int d = 0; d < DH; d++) qs[d][tid] *= inv;
    }

    float o[DH];
#pragma unroll
    for (int d = 0; d < DH; d++) o[d] = 0.f;
    float l = 0.f;

    int kvEnd = q0 + BQ;
    for (int kv0 = 0; kv0 < kvEnd; kv0 += BKV) {
        __syncthreads();
        {
            const float* kp = K + ((size_t)(b * NSEQ + kv0 + tid) * NH + h) * DH;
            const float* vp = V + ((size_t)(b * NSEQ + kv0 + tid) * NH + h) * DH;
            float nrm = 0.f;
#pragma unroll
            for (int d = 0; d < DH; d++) {
                float xv = kp[d];
                ks[d][tid] = xv;
                nrm += xv * xv;
                vs[d][tid] = vp[d];
            }
            float inv = 1.0f / fmaxf(sqrtf(nrm), EPS_L2);
#pragma unroll
            for (int d = 0; d < DH; d++) ks[d][tid] *= inv;
        }
        __syncthreads();

        int jmax = min(BKV, q0 + tid - kv0 + 1);   // causal: global key <= global query
        for (int j = 0; j < jmax; j++) {
            float s0 = 0.f, s1 = 0.f, s2 = 0.f, s3 = 0.f;
#pragma unroll
            for (int d = 0; d < DH; d += 4) {
                s0 += qs[d + 0][tid] * ks[d + 0][j];
                s1 += qs[d + 1][tid] * ks[d + 1][j];
                s2 += qs[d + 2][tid] * ks[d + 2][j];
                s3 += qs[d + 3][tid] * ks[d + 3][j];
            }
            float s = (s0 + s1 + s2 + s3) * ATT_SCALE;
            float p = __expf(s - ATT_SCALE);       // fixed max = 8
            l += p;
#pragma unroll
            for (int d = 0; d < DH; d++) o[d] += p * vs[d][j];
        }
    }

    float inv = 1.0f / l;
    float* op = O + ((size_t)(b * NSEQ + q0 + tid) * NH + h) * DH;
#pragma unroll
    for (int d = 0; d < DH; d++) op[d] = o[d] * inv;
}

// ------------------------- residual + LayerNorm -------------------------
// h = LN(a + h*RES_SCALE) * g + b   (in-place on hb)
__global__ __launch_bounds__(128) void resid_ln_kernel(
    const float* __restrict__ a, float* __restrict__ hb,
    const float* __restrict__ g, const float* __restrict__ bt) {
    __shared__ float red[4];
    int row = blockIdx.x;
    int tid = threadIdx.x;     // 128 threads * 4 = 512
    const float* ar = a + (size_t)row * DMODEL;
    float* hr = hb + (size_t)row * DMODEL;

    float4 av = *(const float4*)&ar[tid * 4];
    float4 hv = *(const float4*)&hr[tid * 4];
    float v0 = av.x + hv.x * RES_SCALE;
    float v1 = av.y + hv.y * RES_SCALE;
    float v2 = av.z + hv.z * RES_SCALE;
    float v3 = av.w + hv.w * RES_SCALE;

    float s = v0 + v1 + v2 + v3;
#pragma unroll
    for (int o = 16; o > 0; o >>= 1) s += __shfl_xor_sync(0xffffffffu, s, o);
    if ((tid & 31) == 0) red[tid >> 5] = s;
    __syncthreads();
    float mean = (red[0] + red[1] + red[2] + red[3]) * (1.0f / DMODEL);

    float d0 = v0 - mean, d1 = v1 - mean, d2 = v2 - mean, d3 = v3 - mean;
    float sq = d0 * d0 + d1 * d1 + d2 * d2 + d3 * d3;
#pragma unroll
    for (int o = 16; o > 0; o >>= 1) sq += __shfl_xor_sync(0xffffffffu, sq, o);
    __syncthreads();
    if ((tid & 31) == 0) red[tid >> 5] = sq;
    __syncthreads();
    float var = (red[0] + red[1] + red[2] + red[3]) * (1.0f / DMODEL);
    float inv = rsqrtf(var + EPS_LN);

    float4 gv = *(const float4*)&g[tid * 4];
    float4 bv = *(const float4*)&bt[tid * 4];
    float4 outv;
    outv.x = d0 * inv * gv.x + bv.x;
    outv.y = d1 * inv * gv.y + bv.y;
    outv.z = d2 * inv * gv.z + bv.z;
    outv.w = d3 * inv * gv.w + bv.w;
    *(float4*)&hr[tid * 4] = outv;
}

// ------------------------- driver -------------------------
extern "C" void kernel_launch(void* const* d_in, const int* in_sizes, int n_in,
                              void* d_out, int out_size) {
    const int*   x    = (const int*)d_in[0];
    const float* tok  = (const float*)d_in[1];
    const float* pos  = (const float*)d_in[2];
    const float* Wq   = (const float*)d_in[3];
    const float* Wk   = (const float*)d_in[4];
    const float* Wv   = (const float*)d_in[5];
    const float* Wo   = (const float*)d_in[6];
    const float* ln1g = (const float*)d_in[7];
    const float* ln1b = (const float*)d_in[8];
    const float* W1   = (const float*)d_in[9];
    const float* W2   = (const float*)d_in[10];
    const float* ln2g = (const float*)d_in[11];
    const float* ln2b = (const float*)d_in[12];
    const float* Wlog = (const float*)d_in[13];
    float* out = (float*)d_out;

    float *h, *q, *k, *v, *o, *ff;
    cudaGetSymbolAddress((void**)&h,  g_h);
    cudaGetSymbolAddress((void**)&q,  g_q);
    cudaGetSymbolAddress((void**)&k,  g_k);
    cudaGetSymbolAddress((void**)&v,  g_v);
    cudaGetSymbolAddress((void**)&o,  g_o);
    cudaGetSymbolAddress((void**)&ff, g_ff);

    embed_kernel<<<MROWS, 128>>>(x, tok, pos);

    const size_t wAttn = (size_t)DMODEL * NH * DH;   // 512*512
    const size_t wFF   = (size_t)DMODEL * DFF;       // 512*2048
    const size_t vecD  = DMODEL;

    dim3 gProj(DMODEL / 128, MROWS / 128);   // (4, 32)
    dim3 gFF1(DFF / 128, MROWS / 128);       // (16, 32)
    dim3 gLog(VOCAB / 128, MROWS / 128);     // (250, 32)
    dim3 gFlash(NSEQ / BQ, BB * NH);         // (32, 16)

    for (int i = 0; i < DEPTH; i++) {
        gemm_kernel<0><<<gProj, 256>>>(h, Wq + i * wAttn, q, MROWS, DMODEL, DMODEL);
        gemm_kernel<0><<<gProj, 256>>>(h, Wk + i * wAttn, k, MROWS, DMODEL, DMODEL);
        gemm_kernel<0><<<gProj, 256>>>(h, Wv + i * wAttn, v, MROWS, DMODEL, DMODEL);
        flash_kernel<<<gFlash, 64>>>(q, k, v, o);
        gemm_kernel<0><<<gProj, 256>>>(o, Wo + i * wAttn, q, MROWS, DMODEL, DMODEL);
        resid_ln_kernel<<<MROWS, 128>>>(q, h, ln1g + i * vecD, ln1b + i * vecD);
        gemm_kernel<1><<<gFF1, 256>>>(h, W1 + i * wFF, ff, MROWS, DFF, DMODEL);
        gemm_kernel<0><<<gProj, 256>>>(ff, W2 + i * wFF, q, MROWS, DMODEL, DFF);
        resid_ln_kernel<<<MROWS, 128>>>(q, h, ln2g + i * vecD, ln2b + i * vecD);
    }

    gemm_kernel<0><<<gLog, 256>>>(h, Wlog, out, MROWS, VOCAB, DMODEL);
}

// round 7
// speedup vs baseline: 1.5916x; 1.5916x over previous
#include <cuda_runtime.h>
#include <math.h>

#define BB 2
#define NSEQ 2048
#define DMODEL 512
#define VOCAB 32000
#define DEPTH 6
#define NH 8
#define DH 64
#define DFF 2048
#define MROWS (BB * NSEQ)          // 4096
#define RES_SCALE 1.8612097182041991f   // (2*6)^0.25
#define ATT_SCALE 8.0f
#define EPS_LN 1e-5f
#define EPS_L2 1e-12f

// -------- scratch (device globals; no runtime allocation allowed) --------
__device__ float g_h[MROWS * DMODEL];
__device__ float g_q[MROWS * DMODEL];
__device__ float g_k[MROWS * DMODEL];
__device__ float g_v[MROWS * DMODEL];
__device__ float g_o[MROWS * DMODEL];
__device__ float g_ff[MROWS * DFF];

// ------------------------- embedding -------------------------
__global__ void embed_kernel(const int* __restrict__ x,
                             const float* __restrict__ tok,
                             const float* __restrict__ pos) {
    int row = blockIdx.x;          // 0..MROWS-1
    int n = row % NSEQ;
    int t = x[row];
    int c = threadIdx.x * 4;       // 128 threads * 4 = 512
    float4 a = *(const float4*)&tok[(size_t)t * DMODEL + c];
    float4 p = *(const float4*)&pos[(size_t)n * DMODEL + c];
    a.x += p.x; a.y += p.y; a.z += p.z; a.w += p.w;
    *(float4*)&g_h[(size_t)row * DMODEL + c] = a;
}

// ------------------------- TF32 tensor-core GEMM -------------------------
// C[M,N] = A[M,K] @ B[K,N], row-major. M%128==0, N%128==0, K%32==0.
// mma.sync.m16n8k8 tf32. 256 threads = 8 warps (2 in M x 4 in N),
// warp tile 64x32 = 4x4 m16n8k8 sub-tiles. EPI: 1 = exact GELU.

__device__ __forceinline__ unsigned f2tf(float x) {
    unsigned r;
    asm("cvt.rna.tf32.f32 %0, %1;" : "=r"(r) : "f"(x));
    return r;
}

#define APAD 36    // 36 % 32 = 4 -> bank(m,k) = 4m+k, conflict-free frag loads
#define BPAD 132   // 132 % 32 = 4 -> bank(k,n) = 4k+n, conflict-free

template <int EPI>
__global__ __launch_bounds__(256) void gemm_tc(
    const float* __restrict__ A, const float* __restrict__ Bw,
    float* __restrict__ C, int Md, int Nd, int Kd) {
    __shared__ unsigned As[128][APAD];   // [m][k]
    __shared__ unsigned Bs[32][BPAD];    // [k][n]

    int rowBase = blockIdx.y * 128;
    int colBase = blockIdx.x * 128;
    int tid = threadIdx.x;
    int warp = tid >> 5;
    int lane = tid & 31;
    int wm = warp >> 2;        // 0..1
    int wn = warp & 3;         // 0..3
    int lr = lane >> 2;        // 0..7
    int lc = lane & 3;         // 0..3

    float acc[4][4][4];        // [mTile][nTile][reg]
#pragma unroll
    for (int i = 0; i < 4; i++)
#pragma unroll
        for (int j = 0; j < 4; j++)
#pragma unroll
            for (int r = 0; r < 4; r++) acc[i][j][r] = 0.f;

    for (int k0 = 0; k0 < Kd; k0 += 32) {
        // ---- load A tile 128x32 (1024 float4), convert to tf32 ----
#pragma unroll
        for (int i = 0; i < 4; i++) {
            int idx = tid + i * 256;
            int r = idx >> 3;              // 0..127
            int c = (idx & 7) * 4;         // 0..28
            float4 a4 = *(const float4*)&A[(size_t)(rowBase + r) * Kd + k0 + c];
            As[r][c + 0] = f2tf(a4.x);
            As[r][c + 1] = f2tf(a4.y);
            As[r][c + 2] = f2tf(a4.z);
            As[r][c + 3] = f2tf(a4.w);
        }
        // ---- load B tile 32x128 ----
#pragma unroll
        for (int i = 0; i < 4; i++) {
            int idx = tid + i * 256;
            int r = idx >> 5;              // 0..31
            int c = (idx & 31) * 4;        // 0..124
            float4 b4 = *(const float4*)&Bw[(size_t)(k0 + r) * Nd + colBase + c];
            Bs[r][c + 0] = f2tf(b4.x);
            Bs[r][c + 1] = f2tf(b4.y);
            Bs[r][c + 2] = f2tf(b4.z);
            Bs[r][c + 3] = f2tf(b4.w);
        }
        __syncthreads();

#pragma unroll
        for (int ks = 0; ks < 32; ks += 8) {
            unsigned af[4][4];   // 4 m-tiles
            unsigned bf[4][2];   // 4 n-tiles
#pragma unroll
            for (int i = 0; i < 4; i++) {
                int m0 = wm * 64 + i * 16;
                af[i][0] = As[m0 + lr][ks + lc];
                af[i][1] = As[m0 + lr + 8][ks + lc];
                af[i][2] = As[m0 + lr][ks + lc + 4];
                af[i][3] = As[m0 + lr + 8][ks + lc + 4];
            }
#pragma unroll
            for (int j = 0; j < 4; j++) {
                int n0 = wn * 32 + j * 8;
                bf[j][0] = Bs[ks + lc][n0 + lr];
                bf[j][1] = Bs[ks + lc + 4][n0 + lr];
            }
#pragma unroll
            for (int i = 0; i < 4; i++)
#pragma unroll
                for (int j = 0; j < 4; j++) {
                    asm volatile(
                        "mma.sync.aligned.m16n8k8.row.col.f32.tf32.tf32.f32 "
                        "{%0,%1,%2,%3}, {%4,%5,%6,%7}, {%8,%9}, {%0,%1,%2,%3};"
                        : "+f"(acc[i][j][0]), "+f"(acc[i][j][1]),
                          "+f"(acc[i][j][2]), "+f"(acc[i][j][3])
                        : "r"(af[i][0]), "r"(af[i][1]), "r"(af[i][2]), "r"(af[i][3]),
                          "r"(bf[j][0]), "r"(bf[j][1]));
                }
        }
        __syncthreads();
    }

    // ---- epilogue ----
    const float gc = 0.70710678118654752f;
#pragma unroll
    for (int i = 0; i < 4; i++) {
#pragma unroll
        for (int j = 0; j < 4; j++) {
            float v0 = acc[i][j][0], v1 = acc[i][j][1];
            float v2 = acc[i][j][2], v3 = acc[i][j][3];
            if (EPI == 1) {
                v0 = 0.5f * v0 * (1.0f + erff(v0 * gc));
                v1 = 0.5f * v1 * (1.0f + erff(v1 * gc));
                v2 = 0.5f * v2 * (1.0f + erff(v2 * gc));
                v3 = 0.5f * v3 * (1.0f + erff(v3 * gc));
            }
            int row = rowBase + wm * 64 + i * 16 + lr;
            int col = colBase + wn * 32 + j * 8 + lc * 2;
            float2 p0 = {v0, v1};
            float2 p1 = {v2, v3};
            *(float2*)&C[(size_t)row * Nd + col] = p0;
            *(float2*)&C[(size_t)(row + 8) * Nd + col] = p1;
        }
    }
}

// ------------------------- fused QKV projection -------------------------
// blockIdx.z selects (Wq->q, Wk->k, Wv->v); one launch = 384 blocks (fills chip)
__global__ __launch_bounds__(256) void qkv_tc(
    const float* __restrict__ A,
    const float* __restrict__ Wq, const float* __restrict__ Wk,
    const float* __restrict__ Wv,
    float* __restrict__ q, float* __restrict__ k, float* __restrict__ v) {
    const float* Bw = (blockIdx.z == 0) ? Wq : (blockIdx.z == 1) ? Wk : Wv;
    float* C = (blockIdx.z == 0) ? q : (blockIdx.z == 1) ? k : v;

    __shared__ unsigned As[128][APAD];
    __shared__ unsigned Bs[32][BPAD];

    int rowBase = blockIdx.y * 128;
    int colBase = blockIdx.x * 128;
    int tid = threadIdx.x;
    int warp = tid >> 5;
    int lane = tid & 31;
    int wm = warp >> 2, wn = warp & 3;
    int lr = lane >> 2, lc = lane & 3;
    const int Nd = DMODEL, Kd = DMODEL;

    float acc[4][4][4];
#pragma unroll
    for (int i = 0; i < 4; i++)
#pragma unroll
        for (int j = 0; j < 4; j++)
#pragma unroll
            for (int r = 0; r < 4; r++) acc[i][j][r] = 0.f;

    for (int k0 = 0; k0 < Kd; k0 += 32) {
#pragma unroll
        for (int i = 0; i < 4; i++) {
            int idx = tid + i * 256;
            int r = idx >> 3, c = (idx & 7) * 4;
            float4 a4 = *(const float4*)&A[(size_t)(rowBase + r) * Kd + k0 + c];
            As[r][c + 0] = f2tf(a4.x); As[r][c + 1] = f2tf(a4.y);
            As[r][c + 2] = f2tf(a4.z); As[r][c + 3] = f2tf(a4.w);
        }
#pragma unroll
        for (int i = 0; i < 4; i++) {
            int idx = tid + i * 256;
            int r = idx >> 5, c = (idx & 31) * 4;
            float4 b4 = *(const float4*)&Bw[(size_t)(k0 + r) * Nd + colBase + c];
            Bs[r][c + 0] = f2tf(b4.x); Bs[r][c + 1] = f2tf(b4.y);
            Bs[r][c + 2] = f2tf(b4.z); Bs[r][c + 3] = f2tf(b4.w);
        }
        __syncthreads();
#pragma unroll
        for (int ks = 0; ks < 32; ks += 8) {
            unsigned af[4][4], bf[4][2];
#pragma unroll
            for (int i = 0; i < 4; i++) {
                int m0 = wm * 64 + i * 16;
                af[i][0] = As[m0 + lr][ks + lc];
                af[i][1] = As[m0 + lr + 8][ks + lc];
                af[i][2] = As[m0 + lr][ks + lc + 4];
                af[i][3] = As[m0 + lr + 8][ks + lc + 4];
            }
#pragma unroll
            for (int j = 0; j < 4; j++) {
                int n0 = wn * 32 + j * 8;
                bf[j][0] = Bs[ks + lc][n0 + lr];
                bf[j][1] = Bs[ks + lc + 4][n0 + lr];
            }
#pragma unroll
            for (int i = 0; i < 4; i++)
#pragma unroll
                for (int j = 0; j < 4; j++) {
                    asm volatile(
                        "mma.sync.aligned.m16n8k8.row.col.f32.tf32.tf32.f32 "
                        "{%0,%1,%2,%3}, {%4,%5,%6,%7}, {%8,%9}, {%0,%1,%2,%3};"
                        : "+f"(acc[i][j][0]), "+f"(acc[i][j][1]),
                          "+f"(acc[i][j][2]), "+f"(acc[i][j][3])
                        : "r"(af[i][0]), "r"(af[i][1]), "r"(af[i][2]), "r"(af[i][3]),
                          "r"(bf[j][0]), "r"(bf[j][1]));
                }
        }
        __syncthreads();
    }
#pragma unroll
    for (int i = 0; i < 4; i++)
#pragma unroll
        for (int j = 0; j < 4; j++) {
            int row = rowBase + wm * 64 + i * 16 + lr;
            int col = colBase + wn * 32 + j * 8 + lc * 2;
            float2 p0 = {acc[i][j][0], acc[i][j][1]};
            float2 p1 = {acc[i][j][2], acc[i][j][3]};
            *(float2*)&C[(size_t)row * Nd + col] = p0;
            *(float2*)&C[(size_t)(row + 8) * Nd + col] = p1;
        }
}

// ------------------------- flash causal attention -------------------------
// Cosine-sim attention: q,k l2-normalized -> scores in [-8,8], so softmax
// uses a FIXED max of 8 (no online rescaling needed; shift-invariant).
#define BQ 64
#define BKV 64
__global__ __launch_bounds__(64) void flash_kernel(
    const float* __restrict__ Q, const float* __restrict__ K,
    const float* __restrict__ V, float* __restrict__ O) {
    __shared__ float qs[DH][BQ];
    __shared__ float ks[DH][BKV];
    __shared__ float vs[DH][BKV];

    int qt = blockIdx.x;
    int bh = blockIdx.y;
    int b = bh / NH, h = bh % NH;
    int tid = threadIdx.x;
    int q0 = qt * BQ;

    {
        const float* qp = Q + ((size_t)(b * NSEQ + q0 + tid) * NH + h) * DH;
        float nrm = 0.f;
#pragma unroll
        for (int d = 0; d < DH; d++) { float xv = qp[d]; qs[d][tid] = xv; nrm += xv * xv; }
        float inv = 1.0f / fmaxf(sqrtf(nrm), EPS_L2);
#pragma unroll
        for (int d = 0; d < DH; d++) qs[d][tid] *= inv;
    }

    float o[DH];
#pragma unroll
    for (int d = 0; d < DH; d++) o[d] = 0.f;
    float l = 0.f;

    int kvEnd = q0 + BQ;
    for (int kv0 = 0; kv0 < kvEnd; kv0 += BKV) {
        __syncthreads();
        {
            const float* kp = K + ((size_t)(b * NSEQ + kv0 + tid) * NH + h) * DH;
            const float* vp = V + ((size_t)(b * NSEQ + kv0 + tid) * NH + h) * DH;
            float nrm = 0.f;
#pragma unroll
            for (int d = 0; d < DH; d++) {
                float xv = kp[d];
                ks[d][tid] = xv;
                nrm += xv * xv;
                vs[d][tid] = vp[d];
            }
            float inv = 1.0f / fmaxf(sqrtf(nrm), EPS_L2);
#pragma unroll
            for (int d = 0; d < DH; d++) ks[d][tid] *= inv;
        }
        __syncthreads();

        int jmax = min(BKV, q0 + tid - kv0 + 1);
        for (int j = 0; j < jmax; j++) {
            float s0 = 0.f, s1 = 0.f, s2 = 0.f, s3 = 0.f;
#pragma unroll
            for (int d = 0; d < DH; d += 4) {
                s0 += qs[d + 0][tid] * ks[d + 0][j];
                s1 += qs[d + 1][tid] * ks[d + 1][j];
                s2 += qs[d + 2][tid] * ks[d + 2][j];
                s3 += qs[d + 3][tid] * ks[d + 3][j];
            }
            float s = (s0 + s1 + s2 + s3) * ATT_SCALE;
            float p = __expf(s - ATT_SCALE);
            l += p;
#pragma unroll
            for (int d = 0; d < DH; d++) o[d] += p * vs[d][j];
        }
    }

    float inv = 1.0f / l;
    float* op = O + ((size_t)(b * NSEQ + q0 + tid) * NH + h) * DH;
#pragma unroll
    for (int d = 0; d < DH; d++) op[d] = o[d] * inv;
}

// ------------------------- residual + LayerNorm -------------------------
__global__ __launch_bounds__(128) void resid_ln_kernel(
    const float* __restrict__ a, float* __restrict__ hb,
    const float* __restrict__ g, const float* __restrict__ bt) {
    __shared__ float red[4];
    int row = blockIdx.x;
    int tid = threadIdx.x;
    const float* ar = a + (size_t)row * DMODEL;
    float* hr = hb + (size_t)row * DMODEL;

    float4 av = *(const float4*)&ar[tid * 4];
    float4 hv = *(const float4*)&hr[tid * 4];
    float v0 = av.x + hv.x * RES_SCALE;
    float v1 = av.y + hv.y * RES_SCALE;
    float v2 = av.z + hv.z * RES_SCALE;
    float v3 = av.w + hv.w * RES_SCALE;

    float s = v0 + v1 + v2 + v3;
#pragma unroll
    for (int o = 16; o > 0; o >>= 1) s += __shfl_xor_sync(0xffffffffu, s, o);
    if ((tid & 31) == 0) red[tid >> 5] = s;
    __syncthreads();
    float mean = (red[0] + red[1] + red[2] + red[3]) * (1.0f / DMODEL);

    float d0 = v0 - mean, d1 = v1 - mean, d2 = v2 - mean, d3 = v3 - mean;
    float sq = d0 * d0 + d1 * d1 + d2 * d2 + d3 * d3;
#pragma unroll
    for (int o = 16; o > 0; o >>= 1) sq += __shfl_xor_sync(0xffffffffu, sq, o);
    __syncthreads();
    if ((tid & 31) == 0) red[tid >> 5] = sq;
    __syncthreads();
    float var = (red[0] + red[1] + red[2] + red[3]) * (1.0f / DMODEL);
    float inv = rsqrtf(var + EPS_LN);

    float4 gv = *(const float4*)&g[tid * 4];
    float4 bv = *(const float4*)&bt[tid * 4];
    float4 outv;
    outv.x = d0 * inv * gv.x + bv.x;
    outv.y = d1 * inv * gv.y + bv.y;
    outv.z = d2 * inv * gv.z + bv.z;
    outv.w = d3 * inv * gv.w + bv.w;
    *(float4*)&hr[tid * 4] = outv;
}

// ------------------------- driver -------------------------
extern "C" void kernel_launch(void* const* d_in, const int* in_sizes, int n_in,
                              void* d_out, int out_size) {
    const int*   x    = (const int*)d_in[0];
    const float* tok  = (const float*)d_in[1];
    const float* pos  = (const float*)d_in[2];
    const float* Wq   = (const float*)d_in[3];
    const float* Wk   = (const float*)d_in[4];
    const float* Wv   = (const float*)d_in[5];
    const float* Wo   = (const float*)d_in[6];
    const float* ln1g = (const float*)d_in[7];
    const float* ln1b = (const float*)d_in[8];
    const float* W1   = (const float*)d_in[9];
    const float* W2   = (const float*)d_in[10];
    const float* ln2g = (const float*)d_in[11];
    const float* ln2b = (const float*)d_in[12];
    const float* Wlog = (const float*)d_in[13];
    float* out = (float*)d_out;

    float *h, *q, *k, *v, *o, *ff;
    cudaGetSymbolAddress((void**)&h,  g_h);
    cudaGetSymbolAddress((void**)&q,  g_q);
    cudaGetSymbolAddress((void**)&k,  g_k);
    cudaGetSymbolAddress((void**)&v,  g_v);
    cudaGetSymbolAddress((void**)&o,  g_o);
    cudaGetSymbolAddress((void**)&ff, g_ff);

    embed_kernel<<<MROWS, 128>>>(x, tok, pos);

    const size_t wAttn = (size_t)DMODEL * NH * DH;
    const size_t wFF   = (size_t)DMODEL * DFF;
    const size_t vecD  = DMODEL;

    dim3 gQKV(DMODEL / 128, MROWS / 128, 3);  // (4, 32, 3)
    dim3 gProj(DMODEL / 128, MROWS / 128);    // (4, 32)
    dim3 gFF1(DFF / 128, MROWS / 128);        // (16, 32)
    dim3 gLog(VOCAB / 128, MROWS / 128);      // (250, 32)
    dim3 gFlash(NSEQ / BQ, BB * NH);          // (32, 16)

    for (int i = 0; i < DEPTH; i++) {
        qkv_tc<<<gQKV, 256>>>(h, Wq + i * wAttn, Wk + i * wAttn, Wv + i * wAttn,
                              q, k, v);
        flash_kernel<<<gFlash, 64>>>(q, k, v, o);
        gemm_tc<0><<<gProj, 256>>>(o, Wo + i * wAttn, q, MROWS, DMODEL, DMODEL);
        resid_ln_kernel<<<MROWS, 128>>>(q, h, ln1g + i * vecD, ln1b + i * vecD);
        gemm_tc<1><<<gFF1, 256>>>(h, W1 + i * wFF, ff, MROWS, DFF, DMODEL);
        gemm_tc<0><<<gProj, 256>>>(ff, W2 + i * wFF, q, MROWS, DMODEL, DFF);
        resid_ln_kernel<<<MROWS, 128>>>(q, h, ln2g + i * vecD, ln2b + i * vecD);
    }

    gemm_tc<0><<<gLog, 256>>>(h, Wlog, out, MROWS, VOCAB, DMODEL);
}

// round 8
// speedup vs baseline: 1.6527x; 1.0384x over previous
#include <cuda_runtime.h>
#include <math.h>

#define BB 2
#define NSEQ 2048
#define DMODEL 512
#define VOCAB 32000
#define DEPTH 6
#define NH 8
#define DH 64
#define DFF 2048
#define MROWS (BB * NSEQ)          // 4096
#define RES_SCALE 1.8612097182041991f   // (2*6)^0.25
#define ATT_SCALE 8.0f
#define EPS_LN 1e-5f
#define EPS_L2 1e-12f

// -------- scratch (device globals; no runtime allocation allowed) --------
__device__ __align__(16) float g_h[MROWS * DMODEL];
__device__ __align__(16) float g_q[MROWS * DMODEL];
__device__ __align__(16) float g_k[MROWS * DMODEL];
__device__ __align__(16) float g_v[MROWS * DMODEL];
__device__ __align__(16) float g_o[MROWS * DMODEL];
__device__ __align__(16) float g_ff[MROWS * DFF];

// ------------------------- embedding -------------------------
__global__ void embed_kernel(const int* __restrict__ x,
                             const float* __restrict__ tok,
                             const float* __restrict__ pos) {
    int row = blockIdx.x;          // 0..MROWS-1
    int n = row % NSEQ;
    int t = x[row];
    int c = threadIdx.x * 4;       // 128 threads * 4 = 512
    float4 a = *(const float4*)&tok[(size_t)t * DMODEL + c];
    float4 p = *(const float4*)&pos[(size_t)n * DMODEL + c];
    a.x += p.x; a.y += p.y; a.z += p.z; a.w += p.w;
    *(float4*)&g_h[(size_t)row * DMODEL + c] = a;
}

// ------------------------- TF32 tensor-core GEMM -------------------------
// C[M,N] = A[M,K] @ B[K,N], row-major. M%128==0, N%128==0, K%32==0.
// Double-buffered cp.async pipeline; cvt to tf32 at fragment-load time
// (numerically identical to converting at SMEM-store time).
// 256 threads = 8 warps (2 M x 4 N); warp tile 64x32 of m16n8k8.

__device__ __forceinline__ unsigned f2tf(float x) {
    unsigned r;
    asm("cvt.rna.tf32.f32 %0, %1;" : "=r"(r) : "f"(x));
    return r;
}

__device__ __forceinline__ void cp16(float* s, const float* g) {
    unsigned sa = (unsigned)__cvta_generic_to_shared(s);
    asm volatile("cp.async.cg.shared.global [%0], [%1], 16;" :: "r"(sa), "l"(g));
}

#define APADF 36    // %32==4 -> bank(m,k)=4m+k, conflict-free; rows 144B (16B-mult)
#define BPADF 132   // %32==4 -> bank(k,n)=4k+n, conflict-free; rows 528B (16B-mult)
#define SMEM_GEMM_BYTES ((2 * 128 * APADF + 2 * 32 * BPADF) * 4)   // 70656

template <int EPI>
__device__ __forceinline__ void gemm_body(
    const float* __restrict__ A, const float* __restrict__ Bw,
    float* __restrict__ C, int Nd, int Kd, int rowBase, int colBase,
    char* smemRaw) {
    float (*As)[128][APADF] = (float(*)[128][APADF])smemRaw;
    float (*Bs)[32][BPADF]  = (float(*)[32][BPADF])(smemRaw + 2 * 128 * APADF * 4);

    int tid = threadIdx.x;
    int warp = tid >> 5, lane = tid & 31;
    int wm = warp >> 2, wn = warp & 3;
    int lr = lane >> 2, lc = lane & 3;

    float acc[4][4][4];
#pragma unroll
    for (int i = 0; i < 4; i++)
#pragma unroll
        for (int j = 0; j < 4; j++)
#pragma unroll
            for (int r = 0; r < 4; r++) acc[i][j][r] = 0.f;

    // ---- prologue: async-load tile 0 ----
#pragma unroll
    for (int i = 0; i < 4; i++) {
        int idx = tid + i * 256;
        int r = idx >> 3, c = (idx & 7) * 4;
        cp16(&As[0][r][c], &A[(size_t)(rowBase + r) * Kd + c]);
    }
#pragma unroll
    for (int i = 0; i < 4; i++) {
        int idx = tid + i * 256;
        int r = idx >> 5, c = (idx & 31) * 4;
        cp16(&Bs[0][r][c], &Bw[(size_t)r * Nd + colBase + c]);
    }
    asm volatile("cp.async.commit_group;");

    int KT = Kd >> 5;
    for (int kt = 0; kt < KT; kt++) {
        if (kt + 1 < KT) {
            int k0 = (kt + 1) << 5;
            int nb = (kt + 1) & 1;
#pragma unroll
            for (int i = 0; i < 4; i++) {
                int idx = tid + i * 256;
                int r = idx >> 3, c = (idx & 7) * 4;
                cp16(&As[nb][r][c], &A[(size_t)(rowBase + r) * Kd + k0 + c]);
            }
#pragma unroll
            for (int i = 0; i < 4; i++) {
                int idx = tid + i * 256;
                int r = idx >> 5, c = (idx & 31) * 4;
                cp16(&Bs[nb][r][c], &Bw[(size_t)(k0 + r) * Nd + colBase + c]);
            }
            asm volatile("cp.async.commit_group;");
            asm volatile("cp.async.wait_group 1;");
        } else {
            asm volatile("cp.async.wait_group 0;");
        }
        __syncthreads();

        int buf = kt & 1;
#pragma unroll
        for (int ks = 0; ks < 32; ks += 8) {
            unsigned af[4][4];
            unsigned bf[4][2];
#pragma unroll
            for (int i = 0; i < 4; i++) {
                int m0 = wm * 64 + i * 16;
                af[i][0] = f2tf(As[buf][m0 + lr][ks + lc]);
                af[i][1] = f2tf(As[buf][m0 + lr + 8][ks + lc]);
                af[i][2] = f2tf(As[buf][m0 + lr][ks + lc + 4]);
                af[i][3] = f2tf(As[buf][m0 + lr + 8][ks + lc + 4]);
            }
#pragma unroll
            for (int j = 0; j < 4; j++) {
                int n0 = wn * 32 + j * 8;
                bf[j][0] = f2tf(Bs[buf][ks + lc][n0 + lr]);
                bf[j][1] = f2tf(Bs[buf][ks + lc + 4][n0 + lr]);
            }
#pragma unroll
            for (int i = 0; i < 4; i++)
#pragma unroll
                for (int j = 0; j < 4; j++) {
                    asm volatile(
                        "mma.sync.aligned.m16n8k8.row.col.f32.tf32.tf32.f32 "
                        "{%0,%1,%2,%3}, {%4,%5,%6,%7}, {%8,%9}, {%0,%1,%2,%3};"
                        : "+f"(acc[i][j][0]), "+f"(acc[i][j][1]),
                          "+f"(acc[i][j][2]), "+f"(acc[i][j][3])
                        : "r"(af[i][0]), "r"(af[i][1]), "r"(af[i][2]), "r"(af[i][3]),
                          "r"(bf[j][0]), "r"(bf[j][1]));
                }
        }
        __syncthreads();
    }

    // ---- epilogue ----
    const float gc = 0.70710678118654752f;
#pragma unroll
    for (int i = 0; i < 4; i++) {
#pragma unroll
        for (int j = 0; j < 4; j++) {
            float v0 = acc[i][j][0], v1 = acc[i][j][1];
            float v2 = acc[i][j][2], v3 = acc[i][j][3];
            if (EPI == 1) {
                v0 = 0.5f * v0 * (1.0f + erff(v0 * gc));
                v1 = 0.5f * v1 * (1.0f + erff(v1 * gc));
                v2 = 0.5f * v2 * (1.0f + erff(v2 * gc));
                v3 = 0.5f * v3 * (1.0f + erff(v3 * gc));
            }
            int row = rowBase + wm * 64 + i * 16 + lr;
            int col = colBase + wn * 32 + j * 8 + lc * 2;
            float2 p0 = {v0, v1};
            float2 p1 = {v2, v3};
            *(float2*)&C[(size_t)row * Nd + col] = p0;
            *(float2*)&C[(size_t)(row + 8) * Nd + col] = p1;
        }
    }
}

template <int EPI>
__global__ __launch_bounds__(256, 2) void gemm_tc(
    const float* __restrict__ A, const float* __restrict__ Bw,
    float* __restrict__ C, int Nd, int Kd) {
    extern __shared__ char sm[];
    gemm_body<EPI>(A, Bw, C, Nd, Kd, blockIdx.y * 128, blockIdx.x * 128, sm);
}

// fused QKV: blockIdx.z selects (Wq->q, Wk->k, Wv->v)
__global__ __launch_bounds__(256, 2) void qkv_tc(
    const float* __restrict__ A,
    const float* __restrict__ Wq, const float* __restrict__ Wk,
    const float* __restrict__ Wv,
    float* __restrict__ q, float* __restrict__ k, float* __restrict__ v) {
    extern __shared__ char sm[];
    const float* Bw = (blockIdx.z == 0) ? Wq : (blockIdx.z == 1) ? Wk : Wv;
    float* C = (blockIdx.z == 0) ? q : (blockIdx.z == 1) ? k : v;
    gemm_body<0>(A, Bw, C, DMODEL, DMODEL, blockIdx.y * 128, blockIdx.x * 128, sm);
}

// ------------------------- flash causal attention -------------------------
// Cosine-sim attention: q,k l2-normalized -> scores in [-8,8], so softmax
// uses a FIXED max of 8 (no online rescaling needed; shift-invariant).
#define BQ 64
#define BKV 64
__global__ __launch_bounds__(64) void flash_kernel(
    const float* __restrict__ Q, const float* __restrict__ K,
    const float* __restrict__ V, float* __restrict__ O) {
    __shared__ float qs[DH][BQ];
    __shared__ float ks[DH][BKV];
    __shared__ float vs[DH][BKV];

    int qt = blockIdx.x;
    int bh = blockIdx.y;
    int b = bh / NH, h = bh % NH;
    int tid = threadIdx.x;
    int q0 = qt * BQ;

    {
        const float* qp = Q + ((size_t)(b * NSEQ + q0 + tid) * NH + h) * DH;
        float nrm = 0.f;
#pragma unroll
        for (int d = 0; d < DH; d++) { float xv = qp[d]; qs[d][tid] = xv; nrm += xv * xv; }
        float inv = 1.0f / fmaxf(sqrtf(nrm), EPS_L2);
#pragma unroll
        for (int d = 0; d < DH; d++) qs[d][tid] *= inv;
    }

    float o[DH];
#pragma unroll
    for (int d = 0; d < DH; d++) o[d] = 0.f;
    float l = 0.f;

    int kvEnd = q0 + BQ;
    for (int kv0 = 0; kv0 < kvEnd; kv0 += BKV) {
        __syncthreads();
        {
            const float* kp = K + ((size_t)(b * NSEQ + kv0 + tid) * NH + h) * DH;
            const float* vp = V + ((size_t)(b * NSEQ + kv0 + tid) * NH + h) * DH;
            float nrm = 0.f;
#pragma unroll
            for (int d = 0; d < DH; d++) {
                float xv = kp[d];
                ks[d][tid] = xv;
                nrm += xv * xv;
                vs[d][tid] = vp[d];
            }
            float inv = 1.0f / fmaxf(sqrtf(nrm), EPS_L2);
#pragma unroll
            for (int d = 0; d < DH; d++) ks[d][tid] *= inv;
        }
        __syncthreads();

        int jmax = min(BKV, q0 + tid - kv0 + 1);
        for (int j = 0; j < jmax; j++) {
            float s0 = 0.f, s1 = 0.f, s2 = 0.f, s3 = 0.f;
#pragma unroll
            for (int d = 0; d < DH; d += 4) {
                s0 += qs[d + 0][tid] * ks[d + 0][j];
                s1 += qs[d + 1][tid] * ks[d + 1][j];
                s2 += qs[d + 2][tid] * ks[d + 2][j];
                s3 += qs[d + 3][tid] * ks[d + 3][j];
            }
            float s = (s0 + s1 + s2 + s3) * ATT_SCALE;
            float p = __expf(s - ATT_SCALE);
            l += p;
#pragma unroll
            for (int d = 0; d < DH; d++) o[d] += p * vs[d][j];
        }
    }

    float inv = 1.0f / l;
    float* op = O + ((size_t)(b * NSEQ + q0 + tid) * NH + h) * DH;
#pragma unroll
    for (int d = 0; d < DH; d++) op[d] = o[d] * inv;
}

// ------------------------- residual + LayerNorm -------------------------
__global__ __launch_bounds__(128) void resid_ln_kernel(
    const float* __restrict__ a, float* __restrict__ hb,
    const float* __restrict__ g, const float* __restrict__ bt) {
    __shared__ float red[4];
    int row = blockIdx.x;
    int tid = threadIdx.x;
    const float* ar = a + (size_t)row * DMODEL;
    float* hr = hb + (size_t)row * DMODEL;

    float4 av = *(const float4*)&ar[tid * 4];
    float4 hv = *(const float4*)&hr[tid * 4];
    float v0 = av.x + hv.x * RES_SCALE;
    float v1 = av.y + hv.y * RES_SCALE;
    float v2 = av.z + hv.z * RES_SCALE;
    float v3 = av.w + hv.w * RES_SCALE;

    float s = v0 + v1 + v2 + v3;
#pragma unroll
    for (int o = 16; o > 0; o >>= 1) s += __shfl_xor_sync(0xffffffffu, s, o);
    if ((tid & 31) == 0) red[tid >> 5] = s;
    __syncthreads();
    float mean = (red[0] + red[1] + red[2] + red[3]) * (1.0f / DMODEL);

    float d0 = v0 - mean, d1 = v1 - mean, d2 = v2 - mean, d3 = v3 - mean;
    float sq = d0 * d0 + d1 * d1 + d2 * d2 + d3 * d3;
#pragma unroll
    for (int o = 16; o > 0; o >>= 1) sq += __shfl_xor_sync(0xffffffffu, sq, o);
    __syncthreads();
    if ((tid & 31) == 0) red[tid >> 5] = sq;
    __syncthreads();
    float var = (red[0] + red[1] + red[2] + red[3]) * (1.0f / DMODEL);
    float inv = rsqrtf(var + EPS_LN);

    float4 gv = *(const float4*)&g[tid * 4];
    float4 bv = *(const float4*)&bt[tid * 4];
    float4 outv;
    outv.x = d0 * inv * gv.x + bv.x;
    outv.y = d1 * inv * gv.y + bv.y;
    outv.z = d2 * inv * gv.z + bv.z;
    outv.w = d3 * inv * gv.w + bv.w;
    *(float4*)&hr[tid * 4] = outv;
}

// ------------------------- driver -------------------------
extern "C" void kernel_launch(void* const* d_in, const int* in_sizes, int n_in,
                              void* d_out, int out_size) {
    const int*   x    = (const int*)d_in[0];
    const float* tok  = (const float*)d_in[1];
    const float* pos  = (const float*)d_in[2];
    const float* Wq   = (const float*)d_in[3];
    const float* Wk   = (const float*)d_in[4];
    const float* Wv   = (const float*)d_in[5];
    const float* Wo   = (const float*)d_in[6];
    const float* ln1g = (const float*)d_in[7];
    const float* ln1b = (const float*)d_in[8];
    const float* W1   = (const float*)d_in[9];
    const float* W2   = (const float*)d_in[10];
    const float* ln2g = (const float*)d_in[11];
    const float* ln2b = (const float*)d_in[12];
    const float* Wlog = (const float*)d_in[13];
    float* out = (float*)d_out;

    float *h, *q, *k, *v, *o, *ff;
    cudaGetSymbolAddress((void**)&h,  g_h);
    cudaGetSymbolAddress((void**)&q,  g_q);
    cudaGetSymbolAddress((void**)&k,  g_k);
    cudaGetSymbolAddress((void**)&v,  g_v);
    cudaGetSymbolAddress((void**)&o,  g_o);
    cudaGetSymbolAddress((void**)&ff, g_ff);

    static int smemSet = 0;
    if (!smemSet) {
        cudaFuncSetAttribute(gemm_tc<0>, cudaFuncAttributeMaxDynamicSharedMemorySize, SMEM_GEMM_BYTES);
        cudaFuncSetAttribute(gemm_tc<1>, cudaFuncAttributeMaxDynamicSharedMemorySize, SMEM_GEMM_BYTES);
        cudaFuncSetAttribute(qkv_tc,     cudaFuncAttributeMaxDynamicSharedMemorySize, SMEM_GEMM_BYTES);
        smemSet = 1;
    }

    embed_kernel<<<MROWS, 128>>>(x, tok, pos);

    const size_t wAttn = (size_t)DMODEL * NH * DH;
    const size_t wFF   = (size_t)DMODEL * DFF;
    const size_t vecD  = DMODEL;

    dim3 gQKV(DMODEL / 128, MROWS / 128, 3);  // (4, 32, 3)
    dim3 gProj(DMODEL / 128, MROWS / 128);    // (4, 32)
    dim3 gFF1(DFF / 128, MROWS / 128);        // (16, 32)
    dim3 gLog(VOCAB / 128, MROWS / 128);      // (250, 32)
    dim3 gFlash(NSEQ / BQ, BB * NH);          // (32, 16)

    for (int i = 0; i < DEPTH; i++) {
        qkv_tc<<<gQKV, 256, SMEM_GEMM_BYTES>>>(h, Wq + i * wAttn, Wk + i * wAttn,
                                               Wv + i * wAttn, q, k, v);
        flash_kernel<<<gFlash, 64>>>(q, k, v, o);
        gemm_tc<0><<<gProj, 256, SMEM_GEMM_BYTES>>>(o, Wo + i * wAttn, q, DMODEL, DMODEL);
        resid_ln_kernel<<<MROWS, 128>>>(q, h, ln1g + i * vecD, ln1b + i * vecD);
        gemm_tc<1><<<gFF1, 256, SMEM_GEMM_BYTES>>>(h, W1 + i * wFF, ff, DFF, DMODEL);
        gemm_tc<0><<<gProj, 256, SMEM_GEMM_BYTES>>>(ff, W2 + i * wFF, q, DMODEL, DFF);
        resid_ln_kernel<<<MROWS, 128>>>(q, h, ln2g + i * vecD, ln2b + i * vecD);
    }

    gemm_tc<0><<<gLog, 256, SMEM_GEMM_BYTES>>>(h, Wlog, out, VOCAB, DMODEL);
}

// round 9
// speedup vs baseline: 4.5188x; 2.7342x over previous
#include <cuda_runtime.h>
#include <math.h>

#define BB 2
#define NSEQ 2048
#define DMODEL 512
#define VOCAB 32000
#define DEPTH 6
#define NH 8
#define DH 64
#define DFF 2048
#define MROWS (BB * NSEQ)          // 4096
#define RES_SCALE 1.8612097182041991f   // (2*6)^0.25
#define ATT_SCALE 8.0f
#define EPS_LN 1e-5f
#define EPS_L2 1e-12f

// -------- scratch (device globals; no runtime allocation allowed) --------
__device__ __align__(16) float g_h[MROWS * DMODEL];
__device__ __align__(16) float g_q[MROWS * DMODEL];
__device__ __align__(16) float g_k[MROWS * DMODEL];
__device__ __align__(16) float g_v[MROWS * DMODEL];
__device__ __align__(16) float g_o[MROWS * DMODEL];
__device__ __align__(16) float g_ff[MROWS * DFF];

// ------------------------- embedding -------------------------
__global__ void embed_kernel(const int* __restrict__ x,
                             const float* __restrict__ tok,
                             const float* __restrict__ pos) {
    int row = blockIdx.x;
    int n = row % NSEQ;
    int t = x[row];
    int c = threadIdx.x * 4;
    float4 a = *(const float4*)&tok[(size_t)t * DMODEL + c];
    float4 p = *(const float4*)&pos[(size_t)n * DMODEL + c];
    a.x += p.x; a.y += p.y; a.z += p.z; a.w += p.w;
    *(float4*)&g_h[(size_t)row * DMODEL + c] = a;
}

// ------------------------- TF32 helpers -------------------------
__device__ __forceinline__ unsigned f2tf(float x) {
    unsigned r;
    asm("cvt.rna.tf32.f32 %0, %1;" : "=r"(r) : "f"(x));
    return r;
}
#define MMA_TF32(ACC, A0, A1, A2, A3, B0, B1)                                \
    asm volatile(                                                            \
        "mma.sync.aligned.m16n8k8.row.col.f32.tf32.tf32.f32 "                \
        "{%0,%1,%2,%3}, {%4,%5,%6,%7}, {%8,%9}, {%0,%1,%2,%3};"              \
        : "+f"((ACC)[0]), "+f"((ACC)[1]), "+f"((ACC)[2]), "+f"((ACC)[3])     \
        : "r"(A0), "r"(A1), "r"(A2), "r"(A3), "r"(B0), "r"(B1))

__device__ __forceinline__ void cp16(float* s, const float* g) {
    unsigned sa = (unsigned)__cvta_generic_to_shared(s);
    asm volatile("cp.async.cg.shared.global [%0], [%1], 16;" :: "r"(sa), "l"(g));
}

// ------------------------- TF32 tensor-core GEMM -------------------------
#define APADF 36
#define BPADF 132
#define SMEM_GEMM_BYTES ((2 * 128 * APADF + 2 * 32 * BPADF) * 4)   // 70656

template <int EPI>
__device__ __forceinline__ void gemm_body(
    const float* __restrict__ A, const float* __restrict__ Bw,
    float* __restrict__ C, int Nd, int Kd, int rowBase, int colBase,
    char* smemRaw) {
    float (*As)[128][APADF] = (float(*)[128][APADF])smemRaw;
    float (*Bs)[32][BPADF]  = (float(*)[32][BPADF])(smemRaw + 2 * 128 * APADF * 4);

    int tid = threadIdx.x;
    int warp = tid >> 5, lane = tid & 31;
    int wm = warp >> 2, wn = warp & 3;
    int lr = lane >> 2, lc = lane & 3;

    float acc[4][4][4];
#pragma unroll
    for (int i = 0; i < 4; i++)
#pragma unroll
        for (int j = 0; j < 4; j++)
#pragma unroll
            for (int r = 0; r < 4; r++) acc[i][j][r] = 0.f;

#pragma unroll
    for (int i = 0; i < 4; i++) {
        int idx = tid + i * 256;
        int r = idx >> 3, c = (idx & 7) * 4;
        cp16(&As[0][r][c], &A[(size_t)(rowBase + r) * Kd + c]);
    }
#pragma unroll
    for (int i = 0; i < 4; i++) {
        int idx = tid + i * 256;
        int r = idx >> 5, c = (idx & 31) * 4;
        cp16(&Bs[0][r][c], &Bw[(size_t)r * Nd + colBase + c]);
    }
    asm volatile("cp.async.commit_group;");

    int KT = Kd >> 5;
    for (int kt = 0; kt < KT; kt++) {
        if (kt + 1 < KT) {
            int k0 = (kt + 1) << 5;
            int nb = (kt + 1) & 1;
#pragma unroll
            for (int i = 0; i < 4; i++) {
                int idx = tid + i * 256;
                int r = idx >> 3, c = (idx & 7) * 4;
                cp16(&As[nb][r][c], &A[(size_t)(rowBase + r) * Kd + k0 + c]);
            }
#pragma unroll
            for (int i = 0; i < 4; i++) {
                int idx = tid + i * 256;
                int r = idx >> 5, c = (idx & 31) * 4;
                cp16(&Bs[nb][r][c], &Bw[(size_t)(k0 + r) * Nd + colBase + c]);
            }
            asm volatile("cp.async.commit_group;");
            asm volatile("cp.async.wait_group 1;");
        } else {
            asm volatile("cp.async.wait_group 0;");
        }
        __syncthreads();

        int buf = kt & 1;
#pragma unroll
        for (int ks = 0; ks < 32; ks += 8) {
            unsigned af[4][4];
            unsigned bf[4][2];
#pragma unroll
            for (int i = 0; i < 4; i++) {
                int m0 = wm * 64 + i * 16;
                af[i][0] = f2tf(As[buf][m0 + lr][ks + lc]);
                af[i][1] = f2tf(As[buf][m0 + lr + 8][ks + lc]);
                af[i][2] = f2tf(As[buf][m0 + lr][ks + lc + 4]);
                af[i][3] = f2tf(As[buf][m0 + lr + 8][ks + lc + 4]);
            }
#pragma unroll
            for (int j = 0; j < 4; j++) {
                int n0 = wn * 32 + j * 8;
                bf[j][0] = f2tf(Bs[buf][ks + lc][n0 + lr]);
                bf[j][1] = f2tf(Bs[buf][ks + lc + 4][n0 + lr]);
            }
#pragma unroll
            for (int i = 0; i < 4; i++)
#pragma unroll
                for (int j = 0; j < 4; j++)
                    MMA_TF32(acc[i][j], af[i][0], af[i][1], af[i][2], af[i][3],
                             bf[j][0], bf[j][1]);
        }
        __syncthreads();
    }

    const float gc = 0.70710678118654752f;
#pragma unroll
    for (int i = 0; i < 4; i++) {
#pragma unroll
        for (int j = 0; j < 4; j++) {
            float v0 = acc[i][j][0], v1 = acc[i][j][1];
            float v2 = acc[i][j][2], v3 = acc[i][j][3];
            if (EPI == 1) {
                v0 = 0.5f * v0 * (1.0f + erff(v0 * gc));
                v1 = 0.5f * v1 * (1.0f + erff(v1 * gc));
                v2 = 0.5f * v2 * (1.0f + erff(v2 * gc));
                v3 = 0.5f * v3 * (1.0f + erff(v3 * gc));
            }
            int row = rowBase + wm * 64 + i * 16 + lr;
            int col = colBase + wn * 32 + j * 8 + lc * 2;
            float2 p0 = {v0, v1};
            float2 p1 = {v2, v3};
            *(float2*)&C[(size_t)row * Nd + col] = p0;
            *(float2*)&C[(size_t)(row + 8) * Nd + col] = p1;
        }
    }
}

template <int EPI>
__global__ __launch_bounds__(256, 2) void gemm_tc(
    const float* __restrict__ A, const float* __restrict__ Bw,
    float* __restrict__ C, int Nd, int Kd) {
    extern __shared__ char sm[];
    gemm_body<EPI>(A, Bw, C, Nd, Kd, blockIdx.y * 128, blockIdx.x * 128, sm);
}

__global__ __launch_bounds__(256, 2) void qkv_tc(
    const float* __restrict__ A,
    const float* __restrict__ Wq, const float* __restrict__ Wk,
    const float* __restrict__ Wv,
    float* __restrict__ q, float* __restrict__ k, float* __restrict__ v) {
    extern __shared__ char sm[];
    const float* Bw = (blockIdx.z == 0) ? Wq : (blockIdx.z == 1) ? Wk : Wv;
    float* C = (blockIdx.z == 0) ? q : (blockIdx.z == 1) ? k : v;
    gemm_body<0>(A, Bw, C, DMODEL, DMODEL, blockIdx.y * 128, blockIdx.x * 128, sm);
}

// ------------------------- TF32 MMA flash attention -------------------------
// 128 threads = 4 warps; block handles 64 queries for one (b,h).
// Fixed softmax max = 8 (scores bounded by SCALE after l2-norm); causal mask
// on the diagonal tile only. P staged via SMEM for the PV MMA.
#define FPAD 68
#define SMEM_FLASH_BYTES (4 * 64 * FPAD * 4)   // 69632

__global__ __launch_bounds__(128, 3) void flash_tc(
    const float* __restrict__ Q, const float* __restrict__ K,
    const float* __restrict__ V, float* __restrict__ O) {
    extern __shared__ float fs[];
    float (*Qs)[FPAD] = (float(*)[FPAD])fs;
    float (*Ks)[FPAD] = (float(*)[FPAD])(fs + 64 * FPAD);
    float (*Vs)[FPAD] = (float(*)[FPAD])(fs + 2 * 64 * FPAD);
    float (*Ps)[FPAD] = (float(*)[FPAD])(fs + 3 * 64 * FPAD);

    int qt = blockIdx.x, bh = blockIdx.y;
    int b = bh >> 3, h = bh & 7;
    int tid = threadIdx.x;
    int warp = tid >> 5, lane = tid & 31;
    int lr = lane >> 2, lc = lane & 3;
    int q0 = qt * 64;
    int lrow = tid >> 1, half = tid & 1;   // 2 threads per row for loads
    int m0 = warp * 16;

    // ---- load + l2-normalize Q tile ----
    {
        const float* qp = Q + (size_t)(b * NSEQ + q0 + lrow) * DMODEL + h * DH + half * 32;
        float buf[32];
        float nrm = 0.f;
#pragma unroll
        for (int i = 0; i < 8; i++) {
            float4 t = ((const float4*)qp)[i];
            buf[i * 4 + 0] = t.x; buf[i * 4 + 1] = t.y;
            buf[i * 4 + 2] = t.z; buf[i * 4 + 3] = t.w;
            nrm += t.x * t.x + t.y * t.y + t.z * t.z + t.w * t.w;
        }
        nrm += __shfl_xor_sync(0xffffffffu, nrm, 1);
        float inv = 1.0f / fmaxf(sqrtf(nrm), EPS_L2);
#pragma unroll
        for (int i = 0; i < 32; i++) Qs[lrow][half * 32 + i] = buf[i] * inv;
    }

    float oacc[8][4];
#pragma unroll
    for (int j = 0; j < 8; j++)
#pragma unroll
        for (int r = 0; r < 4; r++) oacc[j][r] = 0.f;
    float l0 = 0.f, l1 = 0.f;

    for (int kv0 = 0; kv0 <= q0; kv0 += 64) {
        __syncthreads();   // Ks/Vs/Ps reuse; also publishes Qs on first iter
        {
            const float* kp = K + (size_t)(b * NSEQ + kv0 + lrow) * DMODEL + h * DH + half * 32;
            const float* vp = V + (size_t)(b * NSEQ + kv0 + lrow) * DMODEL + h * DH + half * 32;
            float buf[32];
            float nrm = 0.f;
#pragma unroll
            for (int i = 0; i < 8; i++) {
                float4 t = ((const float4*)kp)[i];
                buf[i * 4 + 0] = t.x; buf[i * 4 + 1] = t.y;
                buf[i * 4 + 2] = t.z; buf[i * 4 + 3] = t.w;
                nrm += t.x * t.x + t.y * t.y + t.z * t.z + t.w * t.w;
            }
            nrm += __shfl_xor_sync(0xffffffffu, nrm, 1);
            float inv = 1.0f / fmaxf(sqrtf(nrm), EPS_L2);
#pragma unroll
            for (int i = 0; i < 32; i++) Ks[lrow][half * 32 + i] = buf[i] * inv;
#pragma unroll
            for (int i = 0; i < 8; i++) {
                float4 t = ((const float4*)vp)[i];
                *(float4*)&Vs[lrow][half * 32 + i * 4] = t;
            }
        }
        __syncthreads();

        // ---- S = Qn @ Kn^T (warp: 16 x 64) ----
        float sacc[8][4];
#pragma unroll
        for (int j = 0; j < 8; j++)
#pragma unroll
            for (int r = 0; r < 4; r++) sacc[j][r] = 0.f;
#pragma unroll
        for (int ks = 0; ks < 64; ks += 8) {
            unsigned a0 = f2tf(Qs[m0 + lr][ks + lc]);
            unsigned a1 = f2tf(Qs[m0 + lr + 8][ks + lc]);
            unsigned a2 = f2tf(Qs[m0 + lr][ks + lc + 4]);
            unsigned a3 = f2tf(Qs[m0 + lr + 8][ks + lc + 4]);
#pragma unroll
            for (int j = 0; j < 8; j++) {
                unsigned b0 = f2tf(Ks[j * 8 + lr][ks + lc]);
                unsigned b1 = f2tf(Ks[j * 8 + lr][ks + lc + 4]);
                MMA_TF32(sacc[j], a0, a1, a2, a3, b0, b1);
            }
        }

        // ---- softmax (fixed max = ATT_SCALE), causal mask on diagonal ----
        int r0 = q0 + m0 + lr, r1 = r0 + 8;
        bool diag = (kv0 == q0);
        float lp0 = 0.f, lp1 = 0.f;
#pragma unroll
        for (int j = 0; j < 8; j++) {
            int c = kv0 + j * 8 + 2 * lc;
            float p00 = __expf(ATT_SCALE * sacc[j][0] - ATT_SCALE);
            float p01 = __expf(ATT_SCALE * sacc[j][1] - ATT_SCALE);
            float p10 = __expf(ATT_SCALE * sacc[j][2] - ATT_SCALE);
            float p11 = __expf(ATT_SCALE * sacc[j][3] - ATT_SCALE);
            if (diag) {
                if (c     > r0) p00 = 0.f;
                if (c + 1 > r0) p01 = 0.f;
                if (c     > r1) p10 = 0.f;
                if (c + 1 > r1) p11 = 0.f;
            }
            lp0 += p00 + p01;
            lp1 += p10 + p11;
            Ps[m0 + lr][j * 8 + 2 * lc]     = p00;
            Ps[m0 + lr][j * 8 + 2 * lc + 1] = p01;
            Ps[m0 + lr + 8][j * 8 + 2 * lc]     = p10;
            Ps[m0 + lr + 8][j * 8 + 2 * lc + 1] = p11;
        }
        lp0 += __shfl_xor_sync(0xffffffffu, lp0, 1);
        lp0 += __shfl_xor_sync(0xffffffffu, lp0, 2);
        lp1 += __shfl_xor_sync(0xffffffffu, lp1, 1);
        lp1 += __shfl_xor_sync(0xffffffffu, lp1, 2);
        l0 += lp0;
        l1 += lp1;
        __syncwarp();   // Ps rows are warp-private; warp-level visibility suffices

        // ---- O += P @ V (warp: 16 x 64) ----
#pragma unroll
        for (int ks = 0; ks < 64; ks += 8) {
            unsigned a0 = f2tf(Ps[m0 + lr][ks + lc]);
            unsigned a1 = f2tf(Ps[m0 + lr + 8][ks + lc]);
            unsigned a2 = f2tf(Ps[m0 + lr][ks + lc + 4]);
            unsigned a3 = f2tf(Ps[m0 + lr + 8][ks + lc + 4]);
#pragma unroll
            for (int j = 0; j < 8; j++) {
                unsigned b0 = f2tf(Vs[ks + lc][j * 8 + lr]);
                unsigned b1 = f2tf(Vs[ks + lc + 4][j * 8 + lr]);
                MMA_TF32(oacc[j], a0, a1, a2, a3, b0, b1);
            }
        }
    }

    // ---- epilogue: divide by row sums, write out ----
    float i0 = 1.0f / l0, i1 = 1.0f / l1;
    float* op0 = O + (size_t)(b * NSEQ + q0 + m0 + lr) * DMODEL + h * DH;
    float* op1 = op0 + (size_t)8 * DMODEL;
#pragma unroll
    for (int j = 0; j < 8; j++) {
        float2 p0 = {oacc[j][0] * i0, oacc[j][1] * i0};
        float2 p1 = {oacc[j][2] * i1, oacc[j][3] * i1};
        *(float2*)&op0[j * 8 + 2 * lc] = p0;
        *(float2*)&op1[j * 8 + 2 * lc] = p1;
    }
}

// ------------------------- residual + LayerNorm -------------------------
__global__ __launch_bounds__(128) void resid_ln_kernel(
    const float* __restrict__ a, float* __restrict__ hb,
    const float* __restrict__ g, const float* __restrict__ bt) {
    __shared__ float red[4];
    int row = blockIdx.x;
    int tid = threadIdx.x;
    const float* ar = a + (size_t)row * DMODEL;
    float* hr = hb + (size_t)row * DMODEL;

    float4 av = *(const float4*)&ar[tid * 4];
    float4 hv = *(const float4*)&hr[tid * 4];
    float v0 = av.x + hv.x * RES_SCALE;
    float v1 = av.y + hv.y * RES_SCALE;
    float v2 = av.z + hv.z * RES_SCALE;
    float v3 = av.w + hv.w * RES_SCALE;

    float s = v0 + v1 + v2 + v3;
#pragma unroll
    for (int o = 16; o > 0; o >>= 1) s += __shfl_xor_sync(0xffffffffu, s, o);
    if ((tid & 31) == 0) red[tid >> 5] = s;
    __syncthreads();
    float mean = (red[0] + red[1] + red[2] + red[3]) * (1.0f / DMODEL);

    float d0 = v0 - mean, d1 = v1 - mean, d2 = v2 - mean, d3 = v3 - mean;
    float sq = d0 * d0 + d1 * d1 + d2 * d2 + d3 * d3;
#pragma unroll
    for (int o = 16; o > 0; o >>= 1) sq += __shfl_xor_sync(0xffffffffu, sq, o);
    __syncthreads();
    if ((tid & 31) == 0) red[tid >> 5] = sq;
    __syncthreads();
    float var = (red[0] + red[1] + red[2] + red[3]) * (1.0f / DMODEL);
    float inv = rsqrtf(var + EPS_LN);

    float4 gv = *(const float4*)&g[tid * 4];
    float4 bv = *(const float4*)&bt[tid * 4];
    float4 outv;
    outv.x = d0 * inv * gv.x + bv.x;
    outv.y = d1 * inv * gv.y + bv.y;
    outv.z = d2 * inv * gv.z + bv.z;
    outv.w = d3 * inv * gv.w + bv.w;
    *(float4*)&hr[tid * 4] = outv;
}

// ------------------------- driver -------------------------
extern "C" void kernel_launch(void* const* d_in, const int* in_sizes, int n_in,
                              void* d_out, int out_size) {
    const int*   x    = (const int*)d_in[0];
    const float* tok  = (const float*)d_in[1];
    const float* pos  = (const float*)d_in[2];
    const float* Wq   = (const float*)d_in[3];
    const float* Wk   = (const float*)d_in[4];
    const float* Wv   = (const float*)d_in[5];
    const float* Wo   = (const float*)d_in[6];
    const float* ln1g = (const float*)d_in[7];
    const float* ln1b = (const float*)d_in[8];
    const float* W1   = (const float*)d_in[9];
    const float* W2   = (const float*)d_in[10];
    const float* ln2g = (const float*)d_in[11];
    const float* ln2b = (const float*)d_in[12];
    const float* Wlog = (const float*)d_in[13];
    float* out = (float*)d_out;

    float *h, *q, *k, *v, *o, *ff;
    cudaGetSymbolAddress((void**)&h,  g_h);
    cudaGetSymbolAddress((void**)&q,  g_q);
    cudaGetSymbolAddress((void**)&k,  g_k);
    cudaGetSymbolAddress((void**)&v,  g_v);
    cudaGetSymbolAddress((void**)&o,  g_o);
    cudaGetSymbolAddress((void**)&ff, g_ff);

    static int smemSet = 0;
    if (!smemSet) {
        cudaFuncSetAttribute(gemm_tc<0>, cudaFuncAttributeMaxDynamicSharedMemorySize, SMEM_GEMM_BYTES);
        cudaFuncSetAttribute(gemm_tc<1>, cudaFuncAttributeMaxDynamicSharedMemorySize, SMEM_GEMM_BYTES);
        cudaFuncSetAttribute(qkv_tc,     cudaFuncAttributeMaxDynamicSharedMemorySize, SMEM_GEMM_BYTES);
        cudaFuncSetAttribute(flash_tc,   cudaFuncAttributeMaxDynamicSharedMemorySize, SMEM_FLASH_BYTES);
        smemSet = 1;
    }

    embed_kernel<<<MROWS, 128>>>(x, tok, pos);

    const size_t wAttn = (size_t)DMODEL * NH * DH;
    const size_t wFF   = (size_t)DMODEL * DFF;
    const size_t vecD  = DMODEL;

    dim3 gQKV(DMODEL / 128, MROWS / 128, 3);
    dim3 gProj(DMODEL / 128, MROWS / 128);
    dim3 gFF1(DFF / 128, MROWS / 128);
    dim3 gLog(VOCAB / 128, MROWS / 128);
    dim3 gFlash(NSEQ / 64, BB * NH);

    for (int i = 0; i < DEPTH; i++) {
        qkv_tc<<<gQKV, 256, SMEM_GEMM_BYTES>>>(h, Wq + i * wAttn, Wk + i * wAttn,
                                               Wv + i * wAttn, q, k, v);
        flash_tc<<<gFlash, 128, SMEM_FLASH_BYTES>>>(q, k, v, o);
        gemm_tc<0><<<gProj, 256, SMEM_GEMM_BYTES>>>(o, Wo + i * wAttn, q, DMODEL, DMODEL);
        resid_ln_kernel<<<MROWS, 128>>>(q, h, ln1g + i * vecD, ln1b + i * vecD);
        gemm_tc<1><<<gFF1, 256, SMEM_GEMM_BYTES>>>(h, W1 + i * wFF, ff, DFF, DMODEL);
        gemm_tc<0><<<gProj, 256, SMEM_GEMM_BYTES>>>(ff, W2 + i * wFF, q, DMODEL, DFF);
        resid_ln_kernel<<<MROWS, 128>>>(q, h, ln2g + i * vecD, ln2b + i * vecD);
    }

    gemm_tc<0><<<gLog, 256, SMEM_GEMM_BYTES>>>(h, Wlog, out, VOCAB, DMODEL);
}